// round 1
// baseline (speedup 1.0000x reference)
#include <cuda_runtime.h>

// IF neuron: x [T=4, B=32, H=512, W=1024] fp32.
// Per spatial index i: v=0; for t: v += x[t][i]; s = (v>=1)?1:0; out[t][i]=s; v-=s;
// T is a compile-time constant 4; each thread processes one float4 of spatial
// locations across all 4 timesteps. Pure HBM streaming: 512 MB total traffic.

#define T_STEPS 4
#define SPATIAL (32 * 512 * 1024)          // 16,777,216
#define VEC4    (SPATIAL / 4)              // 4,194,304 threads

__global__ __launch_bounds__(256) void if_neuron_kernel(
    const float4* __restrict__ x, float4* __restrict__ out)
{
    const int i = blockIdx.x * blockDim.x + threadIdx.x;   // float4 index in plane
    // plane stride in float4 units
    const int plane4 = SPATIAL / 4;

    float v0 = 0.f, v1 = 0.f, v2 = 0.f, v3 = 0.f;

#pragma unroll
    for (int t = 0; t < T_STEPS; ++t) {
        float4 xv = x[(size_t)t * plane4 + i];
        v0 += xv.x; v1 += xv.y; v2 += xv.z; v3 += xv.w;

        float4 s;
        s.x = (v0 >= 1.0f) ? 1.0f : 0.0f;
        s.y = (v1 >= 1.0f) ? 1.0f : 0.0f;
        s.z = (v2 >= 1.0f) ? 1.0f : 0.0f;
        s.w = (v3 >= 1.0f) ? 1.0f : 0.0f;

        out[(size_t)t * plane4 + i] = s;

        v0 -= s.x; v1 -= s.y; v2 -= s.z; v3 -= s.w;
    }
}

extern "C" void kernel_launch(void* const* d_in, const int* in_sizes, int n_in,
                              void* d_out, int out_size)
{
    const float4* x = (const float4*)d_in[0];
    float4* out = (float4*)d_out;

    const int threads = 256;
    const int blocks = VEC4 / threads;     // 16384, exact
    if_neuron_kernel<<<blocks, threads>>>(x, out);
}

// round 2
// speedup vs baseline: 1.0086x; 1.0086x over previous
#include <cuda_runtime.h>

// IF neuron: x [T=4, B=32, H=512, W=1024] fp32.
// v=0; for t: v += x[t][i]; s=(v>=1)?1:0; out[t][i]=s; v-=s;
// Pure HBM stream (256 MB read + 256 MB write, zero reuse).
// R2: front-batch all 4 plane loads (MLP=4/thread), streaming cache hints.

#define T_STEPS 4
#define SPATIAL (32 * 512 * 1024)          // 16,777,216
#define PLANE4  (SPATIAL / 4)              // float4 per timestep plane
#define VEC4    (SPATIAL / 4)

__global__ __launch_bounds__(256) void if_neuron_kernel(
    const float4* __restrict__ x, float4* __restrict__ out)
{
    const size_t i = blockIdx.x * (size_t)blockDim.x + threadIdx.x;

    // Front-batch all 4 timestep loads: 4 independent 128-bit streaming loads.
    float4 x0 = __ldcs(x + 0 * (size_t)PLANE4 + i);
    float4 x1 = __ldcs(x + 1 * (size_t)PLANE4 + i);
    float4 x2 = __ldcs(x + 2 * (size_t)PLANE4 + i);
    float4 x3 = __ldcs(x + 3 * (size_t)PLANE4 + i);

    float v0 = 0.f, v1 = 0.f, v2 = 0.f, v3 = 0.f;
    float4 s0, s1, s2, s3;

    // t = 0
    v0 += x0.x; v1 += x0.y; v2 += x0.z; v3 += x0.w;
    s0.x = (v0 >= 1.0f) ? 1.0f : 0.0f;
    s0.y = (v1 >= 1.0f) ? 1.0f : 0.0f;
    s0.z = (v2 >= 1.0f) ? 1.0f : 0.0f;
    s0.w = (v3 >= 1.0f) ? 1.0f : 0.0f;
    v0 -= s0.x; v1 -= s0.y; v2 -= s0.z; v3 -= s0.w;

    // t = 1
    v0 += x1.x; v1 += x1.y; v2 += x1.z; v3 += x1.w;
    s1.x = (v0 >= 1.0f) ? 1.0f : 0.0f;
    s1.y = (v1 >= 1.0f) ? 1.0f : 0.0f;
    s1.z = (v2 >= 1.0f) ? 1.0f : 0.0f;
    s1.w = (v3 >= 1.0f) ? 1.0f : 0.0f;
    v0 -= s1.x; v1 -= s1.y; v2 -= s1.z; v3 -= s1.w;

    // t = 2
    v0 += x2.x; v1 += x2.y; v2 += x2.z; v3 += x2.w;
    s2.x = (v0 >= 1.0f) ? 1.0f : 0.0f;
    s2.y = (v1 >= 1.0f) ? 1.0f : 0.0f;
    s2.z = (v2 >= 1.0f) ? 1.0f : 0.0f;
    s2.w = (v3 >= 1.0f) ? 1.0f : 0.0f;
    v0 -= s2.x; v1 -= s2.y; v2 -= s2.z; v3 -= s2.w;

    // t = 3
    v0 += x3.x; v1 += x3.y; v2 += x3.z; v3 += x3.w;
    s3.x = (v0 >= 1.0f) ? 1.0f : 0.0f;
    s3.y = (v1 >= 1.0f) ? 1.0f : 0.0f;
    s3.z = (v2 >= 1.0f) ? 1.0f : 0.0f;
    s3.w = (v3 >= 1.0f) ? 1.0f : 0.0f;
    // no need to update v after last step

    // Batched streaming stores (write-once, never read back).
    __stcs(out + 0 * (size_t)PLANE4 + i, s0);
    __stcs(out + 1 * (size_t)PLANE4 + i, s1);
    __stcs(out + 2 * (size_t)PLANE4 + i, s2);
    __stcs(out + 3 * (size_t)PLANE4 + i, s3);
}

extern "C" void kernel_launch(void* const* d_in, const int* in_sizes, int n_in,
                              void* d_out, int out_size)
{
    const float4* x = (const float4*)d_in[0];
    float4* out = (float4*)d_out;

    const int threads = 256;
    const int blocks = VEC4 / threads;     // 16384, exact
    if_neuron_kernel<<<blocks, threads>>>(x, out);
}

// round 4
// speedup vs baseline: 1.0140x; 1.0053x over previous
#include <cuda_runtime.h>

// IF neuron: x [T=4, B=32, H=512, W=1024] fp32.
// v=0; for t: v += x[t][i]; s=(v>=1)?1:0; out[t][i]=s; v-=s;
// Pure HBM stream: 256 MB read + 256 MB write.
// R3: 2 float4 per plane per thread -> 8 front-batched loads, 8 back-batched
// stores. Longer per-warp bursts, fewer R/W turnarounds on the DRAM bus.
// (Resubmit: R3 bench died on container infra, no signal obtained.)

#define T_STEPS 4
#define SPATIAL (32 * 512 * 1024)          // 16,777,216 floats per plane
#define PLANE4  (SPATIAL / 4)              // 4,194,304 float4 per plane
#define THREADS 256
#define ITEMS   2                          // float4 per plane per thread
#define BLOCKS  (PLANE4 / (THREADS * ITEMS))   // 8192, exact

__global__ __launch_bounds__(THREADS) void if_neuron_kernel(
    const float4* __restrict__ x, float4* __restrict__ out)
{
    // Block owns a contiguous chunk of THREADS*ITEMS float4s in each plane.
    const size_t base = (size_t)blockIdx.x * (THREADS * ITEMS) + threadIdx.x;

    // ---- front-batched loads: 8 independent 128-bit streaming loads ----
    float4 xv[T_STEPS][ITEMS];
#pragma unroll
    for (int t = 0; t < T_STEPS; ++t)
#pragma unroll
        for (int k = 0; k < ITEMS; ++k)
            xv[t][k] = __ldcs(x + (size_t)t * PLANE4 + base + k * THREADS);

    // ---- IF-neuron scan, registers only ----
    float4 s[T_STEPS][ITEMS];
#pragma unroll
    for (int k = 0; k < ITEMS; ++k) {
        float v0 = 0.f, v1 = 0.f, v2 = 0.f, v3 = 0.f;
#pragma unroll
        for (int t = 0; t < T_STEPS; ++t) {
            v0 += xv[t][k].x; v1 += xv[t][k].y;
            v2 += xv[t][k].z; v3 += xv[t][k].w;
            float4 sv;
            sv.x = (v0 >= 1.0f) ? 1.0f : 0.0f;
            sv.y = (v1 >= 1.0f) ? 1.0f : 0.0f;
            sv.z = (v2 >= 1.0f) ? 1.0f : 0.0f;
            sv.w = (v3 >= 1.0f) ? 1.0f : 0.0f;
            s[t][k] = sv;
            v0 -= sv.x; v1 -= sv.y; v2 -= sv.z; v3 -= sv.w;
        }
    }

    // ---- back-batched stores: 8 streaming stores ----
#pragma unroll
    for (int t = 0; t < T_STEPS; ++t)
#pragma unroll
        for (int k = 0; k < ITEMS; ++k)
            __stcs(out + (size_t)t * PLANE4 + base + k * THREADS, s[t][k]);
}

extern "C" void kernel_launch(void* const* d_in, const int* in_sizes, int n_in,
                              void* d_out, int out_size)
{
    const float4* x = (const float4*)d_in[0];
    float4* out = (float4*)d_out;
    if_neuron_kernel<<<BLOCKS, THREADS>>>(x, out);
}